// round 10
// baseline (speedup 1.0000x reference)
#include <cuda_runtime.h>
#include <cuda_bf16.h>
#include <cstdint>

#define B_    8
#define HW_   128
#define C_    128
#define NPIX  (B_ * HW_ * HW_)   // 131072
#define MTILE 64

// Scratch
__device__ float g_v[(size_t)NPIX * C_];
__device__ __nv_bfloat16 g_xh[(size_t)NPIX * C_];
__device__ __nv_bfloat16 g_xl[(size_t)NPIX * C_];
__device__ __nv_bfloat16 g_aggh[(size_t)NPIX * C_];
__device__ __nv_bfloat16 g_aggl[(size_t)NPIX * C_];
// bf16-split weights, [which][k][n]
__device__ __nv_bfloat16 g_wh[2 * C_ * C_];
__device__ __nv_bfloat16 g_wl[2 * C_ * C_];

__device__ __forceinline__ uint32_t smem_u32(const void* p) {
    uint32_t a;
    asm("{ .reg .u64 t; cvta.to.shared.u64 t, %1; cvt.u32.u64 %0, t; }"
        : "=r"(a) : "l"(p));
    return a;
}
__device__ __forceinline__ void cp_async16(uint32_t dst, const void* src) {
    asm volatile("cp.async.cg.shared.global [%0], [%1], 16;"
                 :: "r"(dst), "l"(src) : "memory");
}
__device__ __forceinline__ void cp_async_wait_all() {
    asm volatile("cp.async.commit_group;" ::: "memory");
    asm volatile("cp.async.wait_group 0;" ::: "memory");
}

// ---------------------------------------------------------------------------
// Weight prep: Wh[k][n], Wl[k][n] = bf16 split of W[k][n]
// ---------------------------------------------------------------------------
__global__ void prep_w(const float* __restrict__ Wv, const float* __restrict__ Wp)
{
    const float* W = blockIdx.x ? Wp : Wv;
    __nv_bfloat16* oh = g_wh + blockIdx.x * C_ * C_;
    __nv_bfloat16* ol = g_wl + blockIdx.x * C_ * C_;
    for (int i = threadIdx.x; i < C_ * C_; i += blockDim.x) {
        float x = W[i];
        __nv_bfloat16 h = __float2bfloat16_rn(x);
        oh[i] = h;
        ol[i] = __float2bfloat16_rn(x - __bfloat162float(h));
    }
}

// ---------------------------------------------------------------------------
// Pre-split x: fp32 -> bf16 hi/lo (pure streaming)
// ---------------------------------------------------------------------------
__global__ void __launch_bounds__(256) split_x(const float4* __restrict__ x,
                                               uint2* __restrict__ xh,
                                               uint2* __restrict__ xl)
{
    const int i = blockIdx.x * 256 + threadIdx.x;   // over NPIX*C/4 float4s
    const float4 a = x[i];
    __nv_bfloat16 h0 = __float2bfloat16_rn(a.x);
    __nv_bfloat16 h1 = __float2bfloat16_rn(a.y);
    __nv_bfloat16 h2 = __float2bfloat16_rn(a.z);
    __nv_bfloat16 h3 = __float2bfloat16_rn(a.w);
    __nv_bfloat16 l0 = __float2bfloat16_rn(a.x - __bfloat162float(h0));
    __nv_bfloat16 l1 = __float2bfloat16_rn(a.y - __bfloat162float(h1));
    __nv_bfloat16 l2 = __float2bfloat16_rn(a.z - __bfloat162float(h2));
    __nv_bfloat16 l3 = __float2bfloat16_rn(a.w - __bfloat162float(h3));
    uint2 hv, lv;
    hv.x = (uint32_t)__bfloat16_as_ushort(h0) | ((uint32_t)__bfloat16_as_ushort(h1) << 16);
    hv.y = (uint32_t)__bfloat16_as_ushort(h2) | ((uint32_t)__bfloat16_as_ushort(h3) << 16);
    lv.x = (uint32_t)__bfloat16_as_ushort(l0) | ((uint32_t)__bfloat16_as_ushort(l1) << 16);
    lv.y = (uint32_t)__bfloat16_as_ushort(l2) | ((uint32_t)__bfloat16_as_ushort(l3) << 16);
    xh[i] = hv;
    xl[i] = lv;
}

// ---------------------------------------------------------------------------
// Tensor-core GEMM (mma.sync bf16 split-x3), 64x64 output tile per CTA.
// 128 threads (4 warps, 2x2 of 32x32 warp tiles). smem 70 KB -> 3 CTAs/SM.
// A pre-split bf16 [m][k]; B pre-split bf16 [k][n] (full n=128, CTA takes
// its 64-col half). blockIdx.x = n-half, blockIdx.y = m-tile.
// ---------------------------------------------------------------------------
#define ASTR 136   // A k-stride (elems); row pitch 272 B (shift-4, conflict-free)
#define BSTR 72    // B n-stride (elems); row pitch 144 B (shift-4, conflict-free)
#define SM_AH 0
#define SM_AL (SM_AH + MTILE * ASTR * 2)         // 17408
#define SM_BH (SM_AL + MTILE * ASTR * 2)         // 34816
#define SM_BL (SM_BH + 128 * BSTR * 2)           // 53248
#define SM_TOTAL (SM_BL + 128 * BSTR * 2)        // 71680

__device__ __forceinline__ void ldsm_x4(uint32_t* r, uint32_t addr) {
    asm volatile("ldmatrix.sync.aligned.m8n8.x4.shared.b16 {%0,%1,%2,%3}, [%4];"
                 : "=r"(r[0]), "=r"(r[1]), "=r"(r[2]), "=r"(r[3]) : "r"(addr));
}
__device__ __forceinline__ void ldsm_x4_t(uint32_t* r, uint32_t addr) {
    asm volatile("ldmatrix.sync.aligned.m8n8.x4.trans.shared.b16 {%0,%1,%2,%3}, [%4];"
                 : "=r"(r[0]), "=r"(r[1]), "=r"(r[2]), "=r"(r[3]) : "r"(addr));
}
__device__ __forceinline__ void mma16816(float* c, const uint32_t* a,
                                         const uint32_t* b) {
    asm volatile(
        "mma.sync.aligned.m16n8k16.row.col.f32.bf16.bf16.f32 "
        "{%0,%1,%2,%3}, {%4,%5,%6,%7}, {%8,%9}, {%0,%1,%2,%3};"
        : "+f"(c[0]), "+f"(c[1]), "+f"(c[2]), "+f"(c[3])
        : "r"(a[0]), "r"(a[1]), "r"(a[2]), "r"(a[3]), "r"(b[0]), "r"(b[1]));
}

__global__ void __launch_bounds__(128, 3)
tc_gemm(const __nv_bfloat16* __restrict__ Ah,
        const __nv_bfloat16* __restrict__ Al,
        const __nv_bfloat16* __restrict__ Wh,
        const __nv_bfloat16* __restrict__ Wl,
        const float* __restrict__ bias,
        float* __restrict__ out)
{
    extern __shared__ char smem[];
    const uint32_t sb = smem_u32(smem);
    const int tid  = threadIdx.x;
    const int lane = tid & 31;
    const int wid  = tid >> 5;
    const int wm   = wid & 1;       // 32-row block (2)
    const int wn   = wid >> 1;      // 32-col block (2)
    const int nhalf = blockIdx.x;   // 0/1
    const size_t mrow = (size_t)blockIdx.y * MTILE;

    // ---- A via cp.async: 64 rows x 256 B per split ----
    const char* ahb = (const char*)(Ah + mrow * C_);
    const char* alb = (const char*)(Al + mrow * C_);
    #pragma unroll
    for (int it = 0; it < 8; it++) {
        const int i = tid + it * 128;          // 0..1023
        const int row = i >> 4, c = i & 15;
        const uint32_t doff = row * (ASTR * 2) + c * 16;
        const int soff = row * 256 + c * 16;
        cp_async16(sb + SM_AH + doff, ahb + soff);
        cp_async16(sb + SM_AL + doff, alb + soff);
    }
    // ---- B via cp.async: 128 rows x 128 B (our 64-col half) per split ----
    const char* whb = (const char*)Wh + nhalf * 128;
    const char* wlb = (const char*)Wl + nhalf * 128;
    #pragma unroll
    for (int it = 0; it < 8; it++) {
        const int i = tid + it * 128;          // 0..1023
        const int row = i >> 3, c = i & 7;
        const uint32_t doff = row * (BSTR * 2) + c * 16;
        const int soff = row * 256 + c * 16;
        cp_async16(sb + SM_BH + doff, whb + soff);
        cp_async16(sb + SM_BL + doff, wlb + soff);
    }
    cp_async_wait_all();
    __syncthreads();

    // ---- Mainloop: k-outer, 3 split-products sharing fragments ----
    float acc[2][4][4];
    #pragma unroll
    for (int h = 0; h < 2; h++)
        #pragma unroll
        for (int j = 0; j < 4; j++)
            #pragma unroll
            for (int e = 0; e < 4; e++) acc[h][j][e] = 0.f;

    const int arow = wm * 32 + (lane & 15);
    const int acol_off = (lane >> 4) * 8;
    const int brow = (lane & 15);
    const int bcol = wn * 32 + (lane >> 4) * 8;

    #pragma unroll
    for (int k0 = 0; k0 < 128; k0 += 16) {
        uint32_t ah[2][4], al[2][4], bh[8], bl[8];
        const uint32_t aoff0 = (arow * ASTR + k0 + acol_off) * 2;
        const uint32_t aoff1 = ((arow + 16) * ASTR + k0 + acol_off) * 2;
        ldsm_x4(ah[0], sb + SM_AH + aoff0);
        ldsm_x4(ah[1], sb + SM_AH + aoff1);
        ldsm_x4(al[0], sb + SM_AL + aoff0);
        ldsm_x4(al[1], sb + SM_AL + aoff1);
        const uint32_t boff0 = ((k0 + brow) * BSTR + bcol) * 2;
        const uint32_t boff1 = ((k0 + brow) * BSTR + bcol + 16) * 2;
        ldsm_x4_t(bh + 0, sb + SM_BH + boff0);
        ldsm_x4_t(bh + 4, sb + SM_BH + boff1);
        ldsm_x4_t(bl + 0, sb + SM_BL + boff0);
        ldsm_x4_t(bl + 4, sb + SM_BL + boff1);

        #pragma unroll
        for (int h = 0; h < 2; h++) {
            mma16816(acc[h][0], ah[h], bh + 0);
            mma16816(acc[h][1], ah[h], bh + 2);
            mma16816(acc[h][2], ah[h], bh + 4);
            mma16816(acc[h][3], ah[h], bh + 6);
            mma16816(acc[h][0], ah[h], bl + 0);
            mma16816(acc[h][1], ah[h], bl + 2);
            mma16816(acc[h][2], ah[h], bl + 4);
            mma16816(acc[h][3], ah[h], bl + 6);
            mma16816(acc[h][0], al[h], bh + 0);
            mma16816(acc[h][1], al[h], bh + 2);
            mma16816(acc[h][2], al[h], bh + 4);
            mma16816(acc[h][3], al[h], bh + 6);
        }
    }

    // ---- Epilogue ----
    const int r0 = wm * 32 + (lane >> 2);
    const int cb = wn * 32 + (lane & 3) * 2;
    float* ob = out + mrow * C_ + nhalf * 64;
    const float* bb = bias + nhalf * 64;
    #pragma unroll
    for (int j = 0; j < 4; j++) {
        const int col = cb + j * 8;
        const float2 bias2 = *(const float2*)(bb + col);
        #pragma unroll
        for (int h = 0; h < 2; h++) {
            float* p0 = ob + (size_t)(r0 + h * 16) * C_ + col;
            float* p1 = ob + (size_t)(r0 + h * 16 + 8) * C_ + col;
            *(float2*)p0 = make_float2(acc[h][j][0] + bias2.x,
                                       acc[h][j][1] + bias2.y);
            *(float2*)p1 = make_float2(acc[h][j][2] + bias2.x,
                                       acc[h][j][3] + bias2.y);
        }
    }
}

// ---------------------------------------------------------------------------
// Superpixel-gated 7x7 neighborhood aggregation. Warp per pixel.
// Output written as bf16 hi/lo split (feeds gemm2 directly).
// ---------------------------------------------------------------------------
__global__ void __launch_bounds__(256) agg_kernel(const float* __restrict__ v,
                                                  const float* __restrict__ attn,
                                                  const int*   __restrict__ sp,
                                                  __nv_bfloat16* __restrict__ outh,
                                                  __nv_bfloat16* __restrict__ outl)
{
    const int lane = threadIdx.x & 31;
    const int wid  = threadIdx.x >> 5;
    const int pix  = blockIdx.x * 8 + wid;
    const int x = pix & 127;
    const int y = (pix >> 7) & 127;
    const int b = pix >> 14;

    const int*   spb = sp + (b << 14);
    const float* vb  = v + (((size_t)b << 14) * C_);
    const int spc = spb[(y << 7) | x];

    int si = y - 3; si = si < 0 ? 0 : (si > HW_ - 7 ? HW_ - 7 : si);
    int sj = x - 3; sj = sj < 0 ? 0 : (sj > HW_ - 7 ? HW_ - 7 : sj);
    const int base_np = si * HW_ + sj;

    int k1 = lane;
    int ki1 = (k1 * 37) >> 8;
    unsigned m0 = __ballot_sync(0xffffffffu,
                                spb[base_np + ki1 * HW_ + (k1 - ki1 * 7)] == spc);
    int k2 = lane + 32; int k2c = k2 > 48 ? 48 : k2;
    int ki2 = (k2c * 37) >> 8;
    unsigned m1 = __ballot_sync(0xffffffffu,
        (k2 < 49) && (spb[base_np + ki2 * HW_ + (k2c - ki2 * 7)] == spc));

    const float* ab = attn +
        ((((size_t)(b * 4 + (lane >> 3)) * HW_ + y) * HW_ + x)) * 49;

    float4 acc = make_float4(0.f, 0.f, 0.f, 0.f);
    while (m0) {
        int k = __ffs(m0) - 1; m0 &= m0 - 1;
        int ki = (k * 37) >> 8;
        int np = base_np + ki * HW_ + (k - ki * 7);
        float a = __ldg(ab + k);
        float4 vv = *(const float4*)(vb + (size_t)np * C_ + lane * 4);
        acc.x += a * vv.x; acc.y += a * vv.y;
        acc.z += a * vv.z; acc.w += a * vv.w;
    }
    while (m1) {
        int k = (__ffs(m1) - 1) + 32; m1 &= m1 - 1;
        int ki = (k * 37) >> 8;
        int np = base_np + ki * HW_ + (k - ki * 7);
        float a = __ldg(ab + k);
        float4 vv = *(const float4*)(vb + (size_t)np * C_ + lane * 4);
        acc.x += a * vv.x; acc.y += a * vv.y;
        acc.z += a * vv.z; acc.w += a * vv.w;
    }

    __nv_bfloat16 h0 = __float2bfloat16_rn(acc.x);
    __nv_bfloat16 h1 = __float2bfloat16_rn(acc.y);
    __nv_bfloat16 h2 = __float2bfloat16_rn(acc.z);
    __nv_bfloat16 h3 = __float2bfloat16_rn(acc.w);
    __nv_bfloat16 l0 = __float2bfloat16_rn(acc.x - __bfloat162float(h0));
    __nv_bfloat16 l1 = __float2bfloat16_rn(acc.y - __bfloat162float(h1));
    __nv_bfloat16 l2 = __float2bfloat16_rn(acc.z - __bfloat162float(h2));
    __nv_bfloat16 l3 = __float2bfloat16_rn(acc.w - __bfloat162float(h3));
    uint2 hv, lv;
    hv.x = (uint32_t)__bfloat16_as_ushort(h0) | ((uint32_t)__bfloat16_as_ushort(h1) << 16);
    hv.y = (uint32_t)__bfloat16_as_ushort(h2) | ((uint32_t)__bfloat16_as_ushort(h3) << 16);
    lv.x = (uint32_t)__bfloat16_as_ushort(l0) | ((uint32_t)__bfloat16_as_ushort(l1) << 16);
    lv.y = (uint32_t)__bfloat16_as_ushort(l2) | ((uint32_t)__bfloat16_as_ushort(l3) << 16);
    *(uint2*)(outh + (size_t)pix * C_ + lane * 4) = hv;
    *(uint2*)(outl + (size_t)pix * C_ + lane * 4) = lv;
}

// ---------------------------------------------------------------------------
// Launch
// ---------------------------------------------------------------------------
extern "C" void kernel_launch(void* const* d_in, const int* in_sizes, int n_in,
                              void* d_out, int out_size)
{
    const float* x    = (const float*)d_in[0];
    const float* attn = (const float*)d_in[1];
    const int*   sp   = (const int*)  d_in[2];
    const float* Wv   = (const float*)d_in[3];
    const float* bv   = (const float*)d_in[4];
    const float* Wp   = (const float*)d_in[5];
    const float* bp   = (const float*)d_in[6];
    float*       out  = (float*)d_out;

    float* vbuf = nullptr;
    __nv_bfloat16 *xh = nullptr, *xl = nullptr;
    __nv_bfloat16 *aggh = nullptr, *aggl = nullptr, *wh = nullptr, *wl = nullptr;
    cudaGetSymbolAddress((void**)&vbuf, g_v);
    cudaGetSymbolAddress((void**)&xh, g_xh);
    cudaGetSymbolAddress((void**)&xl, g_xl);
    cudaGetSymbolAddress((void**)&aggh, g_aggh);
    cudaGetSymbolAddress((void**)&aggl, g_aggl);
    cudaGetSymbolAddress((void**)&wh, g_wh);
    cudaGetSymbolAddress((void**)&wl, g_wl);

    cudaFuncSetAttribute(tc_gemm, cudaFuncAttributeMaxDynamicSharedMemorySize,
                         SM_TOTAL);

    prep_w<<<2, 256>>>(Wv, Wp);
    split_x<<<NPIX * C_ / 4 / 256, 256>>>((const float4*)x, (uint2*)xh, (uint2*)xl);

    dim3 grid(2, NPIX / MTILE);   // (n-half, m-tile)
    tc_gemm<<<grid, 128, SM_TOTAL>>>(xh, xl, wh, wl, bv, vbuf);
    agg_kernel<<<NPIX / 8, 256>>>(vbuf, attn, sp, aggh, aggl);
    tc_gemm<<<grid, 128, SM_TOTAL>>>(aggh, aggl, wh + C_ * C_,
                                     wl + C_ * C_, bp, out);
}

// round 11
// speedup vs baseline: 1.1426x; 1.1426x over previous
#include <cuda_runtime.h>
#include <cuda_bf16.h>
#include <cstdint>

#define B_    8
#define HW_   128
#define C_    128
#define NPIX  (B_ * HW_ * HW_)   // 131072
#define MTILE 64
#define NTILE (NPIX / MTILE)     // 2048
#define GRIDP 296                // 2 CTAs/SM x 148 SMs

// Scratch
__device__ float g_v[(size_t)NPIX * C_];
__device__ __nv_bfloat16 g_aggh[(size_t)NPIX * C_];
__device__ __nv_bfloat16 g_aggl[(size_t)NPIX * C_];
// bf16-split weights, [which][k][n]
__device__ __nv_bfloat16 g_wh[2 * C_ * C_];
__device__ __nv_bfloat16 g_wl[2 * C_ * C_];

__device__ __forceinline__ uint32_t smem_u32(const void* p) {
    uint32_t a;
    asm("{ .reg .u64 t; cvta.to.shared.u64 t, %1; cvt.u32.u64 %0, t; }"
        : "=r"(a) : "l"(p));
    return a;
}
__device__ __forceinline__ void cp_async16(uint32_t dst, const void* src) {
    asm volatile("cp.async.cg.shared.global [%0], [%1], 16;"
                 :: "r"(dst), "l"(src) : "memory");
}
__device__ __forceinline__ void cp_commit() {
    asm volatile("cp.async.commit_group;" ::: "memory");
}
__device__ __forceinline__ void cp_wait0() {
    asm volatile("cp.async.wait_group 0;" ::: "memory");
}

// ---------------------------------------------------------------------------
// Weight prep: Wh[k][n], Wl[k][n] = bf16 split of W[k][n]
// ---------------------------------------------------------------------------
__global__ void prep_w(const float* __restrict__ Wv, const float* __restrict__ Wp)
{
    const float* W = blockIdx.x ? Wp : Wv;
    __nv_bfloat16* oh = g_wh + blockIdx.x * C_ * C_;
    __nv_bfloat16* ol = g_wl + blockIdx.x * C_ * C_;
    for (int i = threadIdx.x; i < C_ * C_; i += blockDim.x) {
        float x = W[i];
        __nv_bfloat16 h = __float2bfloat16_rn(x);
        oh[i] = h;
        ol[i] = __float2bfloat16_rn(x - __bfloat162float(h));
    }
}

// ---------------------------------------------------------------------------
// GEMM common: 64x128 tile, 256 threads, smem 104 KB -> 2 CTAs/SM.
// Persistent: B resident, loop m-tiles with stride GRIDP.
// ---------------------------------------------------------------------------
#define STRIDE 136
#define SM_AH 0
#define SM_AL (SM_AH + MTILE * STRIDE * 2)       // 17408
#define SM_BH (SM_AL + MTILE * STRIDE * 2)       // 34816
#define SM_BL (SM_BH + 128 * STRIDE * 2)         // 69632
#define SM_TOTAL (SM_BL + 128 * STRIDE * 2)      // 104448

__device__ __forceinline__ void ldsm_x4(uint32_t* r, uint32_t addr) {
    asm volatile("ldmatrix.sync.aligned.m8n8.x4.shared.b16 {%0,%1,%2,%3}, [%4];"
                 : "=r"(r[0]), "=r"(r[1]), "=r"(r[2]), "=r"(r[3]) : "r"(addr));
}
__device__ __forceinline__ void ldsm_x4_t(uint32_t* r, uint32_t addr) {
    asm volatile("ldmatrix.sync.aligned.m8n8.x4.trans.shared.b16 {%0,%1,%2,%3}, [%4];"
                 : "=r"(r[0]), "=r"(r[1]), "=r"(r[2]), "=r"(r[3]) : "r"(addr));
}
__device__ __forceinline__ void mma16816(float* c, const uint32_t* a,
                                         const uint32_t* b) {
    asm volatile(
        "mma.sync.aligned.m16n8k16.row.col.f32.bf16.bf16.f32 "
        "{%0,%1,%2,%3}, {%4,%5,%6,%7}, {%8,%9}, {%0,%1,%2,%3};"
        : "+f"(c[0]), "+f"(c[1]), "+f"(c[2]), "+f"(c[3])
        : "r"(a[0]), "r"(a[1]), "r"(a[2]), "r"(a[3]), "r"(b[0]), "r"(b[1]));
}

// Load B (both splits) into smem via cp.async. 256 threads.
__device__ __forceinline__ void load_B_async(uint32_t sb, int tid,
                                             const __nv_bfloat16* Wh,
                                             const __nv_bfloat16* Wl)
{
    #pragma unroll
    for (int it = 0; it < 8; it++) {
        const int i = tid + it * 256;       // 0..2047
        const int row = i >> 4, c = i & 15;
        const uint32_t doff = row * (STRIDE * 2) + c * 16;
        const int soff = row * 256 + c * 16;
        cp_async16(sb + SM_BH + doff, (const char*)Wh + soff);
        cp_async16(sb + SM_BL + doff, (const char*)Wl + soff);
    }
}

// Load A tile t (pre-split bf16) via cp.async. 256 threads.
__device__ __forceinline__ void load_A_async(uint32_t sb, int tid, int t,
                                             const __nv_bfloat16* Ah,
                                             const __nv_bfloat16* Al)
{
    const char* ahb = (const char*)(Ah + (size_t)t * MTILE * C_);
    const char* alb = (const char*)(Al + (size_t)t * MTILE * C_);
    #pragma unroll
    for (int it = 0; it < 4; it++) {
        const int i = tid + it * 256;       // 0..1023
        const int row = i >> 4, c = i & 15;
        const uint32_t doff = row * (STRIDE * 2) + c * 16;
        const int soff = row * 256 + c * 16;
        cp_async16(sb + SM_AH + doff, ahb + soff);
        cp_async16(sb + SM_AL + doff, alb + soff);
    }
}

// Mainloop: fills acc[2][4][4].
__device__ __forceinline__ void gemm_mainloop(uint32_t sb, int lane, int wm,
                                              int wn, float acc[2][4][4])
{
    #pragma unroll
    for (int h = 0; h < 2; h++)
        #pragma unroll
        for (int j = 0; j < 4; j++)
            #pragma unroll
            for (int e = 0; e < 4; e++) acc[h][j][e] = 0.f;

    const int arow = wm * 32 + (lane & 15);
    const int acol_off = (lane >> 4) * 8;
    const int brow = (lane & 15);
    const int bcol = wn * 32 + (lane >> 4) * 8;

    #pragma unroll
    for (int k0 = 0; k0 < 128; k0 += 16) {
        uint32_t ah[2][4], al[2][4], bh[8], bl[8];
        const uint32_t aoff0 = (arow * STRIDE + k0 + acol_off) * 2;
        const uint32_t aoff1 = ((arow + 16) * STRIDE + k0 + acol_off) * 2;
        ldsm_x4(ah[0], sb + SM_AH + aoff0);
        ldsm_x4(ah[1], sb + SM_AH + aoff1);
        ldsm_x4(al[0], sb + SM_AL + aoff0);
        ldsm_x4(al[1], sb + SM_AL + aoff1);
        const uint32_t boff0 = ((k0 + brow) * STRIDE + bcol) * 2;
        const uint32_t boff1 = ((k0 + brow) * STRIDE + bcol + 16) * 2;
        ldsm_x4_t(bh + 0, sb + SM_BH + boff0);
        ldsm_x4_t(bh + 4, sb + SM_BH + boff1);
        ldsm_x4_t(bl + 0, sb + SM_BL + boff0);
        ldsm_x4_t(bl + 4, sb + SM_BL + boff1);

        #pragma unroll
        for (int h = 0; h < 2; h++) {
            mma16816(acc[h][0], ah[h], bh + 0);
            mma16816(acc[h][1], ah[h], bh + 2);
            mma16816(acc[h][2], ah[h], bh + 4);
            mma16816(acc[h][3], ah[h], bh + 6);
            mma16816(acc[h][0], ah[h], bl + 0);
            mma16816(acc[h][1], ah[h], bl + 2);
            mma16816(acc[h][2], ah[h], bl + 4);
            mma16816(acc[h][3], ah[h], bl + 6);
            mma16816(acc[h][0], al[h], bh + 0);
            mma16816(acc[h][1], al[h], bh + 2);
            mma16816(acc[h][2], al[h], bh + 4);
            mma16816(acc[h][3], al[h], bh + 6);
        }
    }
}

__device__ __forceinline__ void gemm_epilogue(int lane, int wm, int wn,
                                              const float acc[2][4][4],
                                              const float2* bias2, float* ob)
{
    const int r0 = wm * 32 + (lane >> 2);
    const int cb = wn * 32 + (lane & 3) * 2;
    #pragma unroll
    for (int j = 0; j < 4; j++) {
        const int col = cb + j * 8;
        #pragma unroll
        for (int h = 0; h < 2; h++) {
            float* p0 = ob + (size_t)(r0 + h * 16) * C_ + col;
            float* p1 = ob + (size_t)(r0 + h * 16 + 8) * C_ + col;
            *(float2*)p0 = make_float2(acc[h][j][0] + bias2[j].x,
                                       acc[h][j][1] + bias2[j].y);
            *(float2*)p1 = make_float2(acc[h][j][2] + bias2[j].x,
                                       acc[h][j][3] + bias2[j].y);
        }
    }
}

// ---------------------------------------------------------------------------
// GEMM2 (persistent, bf16 pre-split A from agg)
// ---------------------------------------------------------------------------
__global__ void __launch_bounds__(256, 2)
tc_gemm_bf_p(const __nv_bfloat16* __restrict__ Ah,
             const __nv_bfloat16* __restrict__ Al,
             const __nv_bfloat16* __restrict__ Wh,
             const __nv_bfloat16* __restrict__ Wl,
             const float* __restrict__ bias,
             float* __restrict__ out)
{
    extern __shared__ char smem[];
    const uint32_t sb = smem_u32(smem);
    const int tid  = threadIdx.x;
    const int lane = tid & 31;
    const int wid  = tid >> 5;
    const int wm   = wid & 1;
    const int wn   = wid >> 1;

    const int cb = wn * 32 + (lane & 3) * 2;
    float2 bias2[4];
    #pragma unroll
    for (int j = 0; j < 4; j++) bias2[j] = *(const float2*)(bias + cb + j * 8);

    load_B_async(sb, tid, Wh, Wl);
    int t = blockIdx.x;
    load_A_async(sb, tid, t, Ah, Al);
    cp_commit(); cp_wait0();
    __syncthreads();

    for (; t < NTILE; t += GRIDP) {
        float acc[2][4][4];
        gemm_mainloop(sb, lane, wm, wn, acc);
        __syncthreads();                        // A consumed

        const int tn = t + GRIDP;
        if (tn < NTILE) load_A_async(sb, tid, tn, Ah, Al);
        cp_commit();

        gemm_epilogue(lane, wm, wn, acc, bias2,
                      out + (size_t)t * MTILE * C_);   // overlaps A cp.async

        cp_wait0();
        __syncthreads();
    }
}

// ---------------------------------------------------------------------------
// GEMM1 (persistent, fp32 A converted in-kernel; LDGs issued before epilogue)
// ---------------------------------------------------------------------------
__device__ __forceinline__ void convert_store_A(char* smem, const float4* ra,
                                                int tid) {
    #pragma unroll
    for (int it = 0; it < 8; it++) {
        const int i = tid + it * 256;       // 0..2047
        const int row = i >> 5, c4 = i & 31;
        const float4 a = ra[it];
        __nv_bfloat16 h0 = __float2bfloat16_rn(a.x);
        __nv_bfloat16 h1 = __float2bfloat16_rn(a.y);
        __nv_bfloat16 h2 = __float2bfloat16_rn(a.z);
        __nv_bfloat16 h3 = __float2bfloat16_rn(a.w);
        __nv_bfloat16 l0 = __float2bfloat16_rn(a.x - __bfloat162float(h0));
        __nv_bfloat16 l1 = __float2bfloat16_rn(a.y - __bfloat162float(h1));
        __nv_bfloat16 l2 = __float2bfloat16_rn(a.z - __bfloat162float(h2));
        __nv_bfloat16 l3 = __float2bfloat16_rn(a.w - __bfloat162float(h3));
        uint64_t hv = (uint64_t)__bfloat16_as_ushort(h0)
                    | ((uint64_t)__bfloat16_as_ushort(h1) << 16)
                    | ((uint64_t)__bfloat16_as_ushort(h2) << 32)
                    | ((uint64_t)__bfloat16_as_ushort(h3) << 48);
        uint64_t lv = (uint64_t)__bfloat16_as_ushort(l0)
                    | ((uint64_t)__bfloat16_as_ushort(l1) << 16)
                    | ((uint64_t)__bfloat16_as_ushort(l2) << 32)
                    | ((uint64_t)__bfloat16_as_ushort(l3) << 48);
        const uint32_t off = row * (STRIDE * 2) + c4 * 8;
        *(uint64_t*)(smem + SM_AH + off) = hv;
        *(uint64_t*)(smem + SM_AL + off) = lv;
    }
}

__global__ void __launch_bounds__(256, 2)
tc_gemm_f32_p(const float* __restrict__ A,
              const __nv_bfloat16* __restrict__ Wh,
              const __nv_bfloat16* __restrict__ Wl,
              const float* __restrict__ bias,
              float* __restrict__ out)
{
    extern __shared__ char smem[];
    const uint32_t sb = smem_u32(smem);
    const int tid  = threadIdx.x;
    const int lane = tid & 31;
    const int wid  = tid >> 5;
    const int wm   = wid & 1;
    const int wn   = wid >> 1;

    const int cb = wn * 32 + (lane & 3) * 2;
    float2 bias2[4];
    #pragma unroll
    for (int j = 0; j < 4; j++) bias2[j] = *(const float2*)(bias + cb + j * 8);

    load_B_async(sb, tid, Wh, Wl);
    cp_commit();

    int t = blockIdx.x;
    float4 ra[8];
    {
        const float4* Ab = (const float4*)(A + (size_t)t * MTILE * C_);
        #pragma unroll
        for (int it = 0; it < 8; it++) ra[it] = Ab[tid + it * 256];
    }
    convert_store_A(smem, ra, tid);
    cp_wait0();
    __syncthreads();

    for (; t < NTILE; t += GRIDP) {
        float acc[2][4][4];
        gemm_mainloop(sb, lane, wm, wn, acc);
        __syncthreads();                        // A consumed

        const int tn = t + GRIDP;
        if (tn < NTILE) {                       // issue LDGs (latency behind epilogue)
            const float4* Ab = (const float4*)(A + (size_t)tn * MTILE * C_);
            #pragma unroll
            for (int it = 0; it < 8; it++) ra[it] = Ab[tid + it * 256];
        }

        gemm_epilogue(lane, wm, wn, acc, bias2,
                      out + (size_t)t * MTILE * C_);

        if (tn < NTILE) convert_store_A(smem, ra, tid);
        __syncthreads();
    }
}

// ---------------------------------------------------------------------------
// Superpixel-gated 7x7 neighborhood aggregation. Warp per pixel.
// Output written as bf16 hi/lo split (feeds gemm2 directly).
// ---------------------------------------------------------------------------
__global__ void __launch_bounds__(256) agg_kernel(const float* __restrict__ v,
                                                  const float* __restrict__ attn,
                                                  const int*   __restrict__ sp,
                                                  __nv_bfloat16* __restrict__ outh,
                                                  __nv_bfloat16* __restrict__ outl)
{
    const int lane = threadIdx.x & 31;
    const int wid  = threadIdx.x >> 5;
    const int pix  = blockIdx.x * 8 + wid;
    const int x = pix & 127;
    const int y = (pix >> 7) & 127;
    const int b = pix >> 14;

    const int*   spb = sp + (b << 14);
    const float* vb  = v + (((size_t)b << 14) * C_);
    const int spc = spb[(y << 7) | x];

    int si = y - 3; si = si < 0 ? 0 : (si > HW_ - 7 ? HW_ - 7 : si);
    int sj = x - 3; sj = sj < 0 ? 0 : (sj > HW_ - 7 ? HW_ - 7 : sj);
    const int base_np = si * HW_ + sj;

    int k1 = lane;
    int ki1 = (k1 * 37) >> 8;
    unsigned m0 = __ballot_sync(0xffffffffu,
                                spb[base_np + ki1 * HW_ + (k1 - ki1 * 7)] == spc);
    int k2 = lane + 32; int k2c = k2 > 48 ? 48 : k2;
    int ki2 = (k2c * 37) >> 8;
    unsigned m1 = __ballot_sync(0xffffffffu,
        (k2 < 49) && (spb[base_np + ki2 * HW_ + (k2c - ki2 * 7)] == spc));

    const float* ab = attn +
        ((((size_t)(b * 4 + (lane >> 3)) * HW_ + y) * HW_ + x)) * 49;

    float4 acc = make_float4(0.f, 0.f, 0.f, 0.f);
    while (m0) {
        int k = __ffs(m0) - 1; m0 &= m0 - 1;
        int ki = (k * 37) >> 8;
        int np = base_np + ki * HW_ + (k - ki * 7);
        float a = __ldg(ab + k);
        float4 vv = *(const float4*)(vb + (size_t)np * C_ + lane * 4);
        acc.x += a * vv.x; acc.y += a * vv.y;
        acc.z += a * vv.z; acc.w += a * vv.w;
    }
    while (m1) {
        int k = (__ffs(m1) - 1) + 32; m1 &= m1 - 1;
        int ki = (k * 37) >> 8;
        int np = base_np + ki * HW_ + (k - ki * 7);
        float a = __ldg(ab + k);
        float4 vv = *(const float4*)(vb + (size_t)np * C_ + lane * 4);
        acc.x += a * vv.x; acc.y += a * vv.y;
        acc.z += a * vv.z; acc.w += a * vv.w;
    }

    __nv_bfloat16 h0 = __float2bfloat16_rn(acc.x);
    __nv_bfloat16 h1 = __float2bfloat16_rn(acc.y);
    __nv_bfloat16 h2 = __float2bfloat16_rn(acc.z);
    __nv_bfloat16 h3 = __float2bfloat16_rn(acc.w);
    __nv_bfloat16 l0 = __float2bfloat16_rn(acc.x - __bfloat162float(h0));
    __nv_bfloat16 l1 = __float2bfloat16_rn(acc.y - __bfloat162float(h1));
    __nv_bfloat16 l2 = __float2bfloat16_rn(acc.z - __bfloat162float(h2));
    __nv_bfloat16 l3 = __float2bfloat16_rn(acc.w - __bfloat162float(h3));
    uint2 hv, lv;
    hv.x = (uint32_t)__bfloat16_as_ushort(h0) | ((uint32_t)__bfloat16_as_ushort(h1) << 16);
    hv.y = (uint32_t)__bfloat16_as_ushort(h2) | ((uint32_t)__bfloat16_as_ushort(h3) << 16);
    lv.x = (uint32_t)__bfloat16_as_ushort(l0) | ((uint32_t)__bfloat16_as_ushort(l1) << 16);
    lv.y = (uint32_t)__bfloat16_as_ushort(l2) | ((uint32_t)__bfloat16_as_ushort(l3) << 16);
    *(uint2*)(outh + (size_t)pix * C_ + lane * 4) = hv;
    *(uint2*)(outl + (size_t)pix * C_ + lane * 4) = lv;
}

// ---------------------------------------------------------------------------
// Launch
// ---------------------------------------------------------------------------
extern "C" void kernel_launch(void* const* d_in, const int* in_sizes, int n_in,
                              void* d_out, int out_size)
{
    const float* x    = (const float*)d_in[0];
    const float* attn = (const float*)d_in[1];
    const int*   sp   = (const int*)  d_in[2];
    const float* Wv   = (const float*)d_in[3];
    const float* bv   = (const float*)d_in[4];
    const float* Wp   = (const float*)d_in[5];
    const float* bp   = (const float*)d_in[6];
    float*       out  = (float*)d_out;

    float* vbuf = nullptr;
    __nv_bfloat16 *aggh = nullptr, *aggl = nullptr, *wh = nullptr, *wl = nullptr;
    cudaGetSymbolAddress((void**)&vbuf, g_v);
    cudaGetSymbolAddress((void**)&aggh, g_aggh);
    cudaGetSymbolAddress((void**)&aggl, g_aggl);
    cudaGetSymbolAddress((void**)&wh, g_wh);
    cudaGetSymbolAddress((void**)&wl, g_wl);

    cudaFuncSetAttribute(tc_gemm_f32_p, cudaFuncAttributeMaxDynamicSharedMemorySize, SM_TOTAL);
    cudaFuncSetAttribute(tc_gemm_bf_p, cudaFuncAttributeMaxDynamicSharedMemorySize, SM_TOTAL);

    prep_w<<<2, 256>>>(Wv, Wp);
    tc_gemm_f32_p<<<GRIDP, 256, SM_TOTAL>>>(x, wh, wl, bv, vbuf);
    agg_kernel<<<NPIX / 8, 256>>>(vbuf, attn, sp, aggh, aggl);
    tc_gemm_bf_p<<<GRIDP, 256, SM_TOTAL>>>(aggh, aggl, wh + C_ * C_,
                                           wl + C_ * C_, bp, out);
}

// round 12
// speedup vs baseline: 1.1685x; 1.0227x over previous
#include <cuda_runtime.h>
#include <cuda_bf16.h>
#include <cstdint>

#define B_    8
#define HW_   128
#define C_    128
#define NPIX  (B_ * HW_ * HW_)   // 131072
#define MTILE 64
#define NTILE (NPIX / MTILE)     // 2048
#define GRIDP 148                // 1 persistent CTA per SM

// Scratch
__device__ float g_v[(size_t)NPIX * C_];
__device__ __nv_bfloat16 g_aggh[(size_t)NPIX * C_];
__device__ __nv_bfloat16 g_aggl[(size_t)NPIX * C_];
// bf16-split weights, [which][k][n]
__device__ __nv_bfloat16 g_wh[2 * C_ * C_];
__device__ __nv_bfloat16 g_wl[2 * C_ * C_];

__device__ __forceinline__ uint32_t smem_u32(const void* p) {
    uint32_t a;
    asm("{ .reg .u64 t; cvta.to.shared.u64 t, %1; cvt.u32.u64 %0, t; }"
        : "=r"(a) : "l"(p));
    return a;
}
__device__ __forceinline__ void cp_async16(uint32_t dst, const void* src) {
    asm volatile("cp.async.cg.shared.global [%0], [%1], 16;"
                 :: "r"(dst), "l"(src) : "memory");
}
__device__ __forceinline__ void cp_commit() {
    asm volatile("cp.async.commit_group;" ::: "memory");
}
__device__ __forceinline__ void cp_wait0() {
    asm volatile("cp.async.wait_group 0;" ::: "memory");
}

// ---------------------------------------------------------------------------
// Weight prep: Wh[k][n], Wl[k][n] = bf16 split of W[k][n]
// ---------------------------------------------------------------------------
__global__ void prep_w(const float* __restrict__ Wv, const float* __restrict__ Wp)
{
    const float* W = blockIdx.x ? Wp : Wv;
    __nv_bfloat16* oh = g_wh + blockIdx.x * C_ * C_;
    __nv_bfloat16* ol = g_wl + blockIdx.x * C_ * C_;
    for (int i = threadIdx.x; i < C_ * C_; i += blockDim.x) {
        float x = W[i];
        __nv_bfloat16 h = __float2bfloat16_rn(x);
        oh[i] = h;
        ol[i] = __float2bfloat16_rn(x - __bfloat162float(h));
    }
}

// ---------------------------------------------------------------------------
// GEMM layout: 64x128 tile, 256 threads (8 warps of 32x32), persistent CTA,
// B resident, A DOUBLE-BUFFERED. smem 139 KB -> 1 CTA/SM.
// ---------------------------------------------------------------------------
#define STRIDE 136
#define ABUF   (MTILE * STRIDE * 2)          // 17408 per split
#define SM_A0  0                             // buf0: AH @0, AL @ABUF
#define SM_A1  (2 * ABUF)                    // buf1: AH, AL
#define SM_BH  (4 * ABUF)                    // 69632
#define SM_BL  (SM_BH + 128 * STRIDE * 2)    // 104448
#define SM_TOTAL (SM_BL + 128 * STRIDE * 2)  // 139264

__device__ __forceinline__ void ldsm_x4(uint32_t* r, uint32_t addr) {
    asm volatile("ldmatrix.sync.aligned.m8n8.x4.shared.b16 {%0,%1,%2,%3}, [%4];"
                 : "=r"(r[0]), "=r"(r[1]), "=r"(r[2]), "=r"(r[3]) : "r"(addr));
}
__device__ __forceinline__ void ldsm_x4_t(uint32_t* r, uint32_t addr) {
    asm volatile("ldmatrix.sync.aligned.m8n8.x4.trans.shared.b16 {%0,%1,%2,%3}, [%4];"
                 : "=r"(r[0]), "=r"(r[1]), "=r"(r[2]), "=r"(r[3]) : "r"(addr));
}
__device__ __forceinline__ void mma16816(float* c, const uint32_t* a,
                                         const uint32_t* b) {
    asm volatile(
        "mma.sync.aligned.m16n8k16.row.col.f32.bf16.bf16.f32 "
        "{%0,%1,%2,%3}, {%4,%5,%6,%7}, {%8,%9}, {%0,%1,%2,%3};"
        : "+f"(c[0]), "+f"(c[1]), "+f"(c[2]), "+f"(c[3])
        : "r"(a[0]), "r"(a[1]), "r"(a[2]), "r"(a[3]), "r"(b[0]), "r"(b[1]));
}

// Load B (both splits) via cp.async. 256 threads.
__device__ __forceinline__ void load_B_async(uint32_t sb, int tid,
                                             const __nv_bfloat16* Wh,
                                             const __nv_bfloat16* Wl)
{
    #pragma unroll
    for (int it = 0; it < 8; it++) {
        const int i = tid + it * 256;       // 0..2047
        const int row = i >> 4, c = i & 15;
        const uint32_t doff = row * (STRIDE * 2) + c * 16;
        const int soff = row * 256 + c * 16;
        cp_async16(sb + SM_BH + doff, (const char*)Wh + soff);
        cp_async16(sb + SM_BL + doff, (const char*)Wl + soff);
    }
}

// Load A tile t (pre-split bf16) via cp.async into buffer at abase.
__device__ __forceinline__ void load_A_async(uint32_t abase, int tid, int t,
                                             const __nv_bfloat16* Ah,
                                             const __nv_bfloat16* Al)
{
    const char* ahb = (const char*)(Ah + (size_t)t * MTILE * C_);
    const char* alb = (const char*)(Al + (size_t)t * MTILE * C_);
    #pragma unroll
    for (int it = 0; it < 4; it++) {
        const int i = tid + it * 256;       // 0..1023
        const int row = i >> 4, c = i & 15;
        const uint32_t doff = row * (STRIDE * 2) + c * 16;
        const int soff = row * 256 + c * 16;
        cp_async16(abase + doff, ahb + soff);
        cp_async16(abase + ABUF + doff, alb + soff);
    }
}

// Mainloop: A at abase (AH @0, AL @ABUF), B fixed at sb+SM_BH/SM_BL.
__device__ __forceinline__ void gemm_mainloop(uint32_t abase, uint32_t sb,
                                              int lane, int wm, int wn,
                                              float acc[2][4][4])
{
    #pragma unroll
    for (int h = 0; h < 2; h++)
        #pragma unroll
        for (int j = 0; j < 4; j++)
            #pragma unroll
            for (int e = 0; e < 4; e++) acc[h][j][e] = 0.f;

    const int arow = wm * 32 + (lane & 15);
    const int acol_off = (lane >> 4) * 8;
    const int brow = (lane & 15);
    const int bcol = wn * 32 + (lane >> 4) * 8;

    #pragma unroll
    for (int k0 = 0; k0 < 128; k0 += 16) {
        uint32_t ah[2][4], al[2][4], bh[8], bl[8];
        const uint32_t aoff0 = (arow * STRIDE + k0 + acol_off) * 2;
        const uint32_t aoff1 = ((arow + 16) * STRIDE + k0 + acol_off) * 2;
        ldsm_x4(ah[0], abase + aoff0);
        ldsm_x4(ah[1], abase + aoff1);
        ldsm_x4(al[0], abase + ABUF + aoff0);
        ldsm_x4(al[1], abase + ABUF + aoff1);
        const uint32_t boff0 = ((k0 + brow) * STRIDE + bcol) * 2;
        const uint32_t boff1 = ((k0 + brow) * STRIDE + bcol + 16) * 2;
        ldsm_x4_t(bh + 0, sb + SM_BH + boff0);
        ldsm_x4_t(bh + 4, sb + SM_BH + boff1);
        ldsm_x4_t(bl + 0, sb + SM_BL + boff0);
        ldsm_x4_t(bl + 4, sb + SM_BL + boff1);

        #pragma unroll
        for (int h = 0; h < 2; h++) {
            mma16816(acc[h][0], ah[h], bh + 0);
            mma16816(acc[h][1], ah[h], bh + 2);
            mma16816(acc[h][2], ah[h], bh + 4);
            mma16816(acc[h][3], ah[h], bh + 6);
            mma16816(acc[h][0], ah[h], bl + 0);
            mma16816(acc[h][1], ah[h], bl + 2);
            mma16816(acc[h][2], ah[h], bl + 4);
            mma16816(acc[h][3], ah[h], bl + 6);
            mma16816(acc[h][0], al[h], bh + 0);
            mma16816(acc[h][1], al[h], bh + 2);
            mma16816(acc[h][2], al[h], bh + 4);
            mma16816(acc[h][3], al[h], bh + 6);
        }
    }
}

__device__ __forceinline__ void gemm_epilogue(int lane, int wm, int wn,
                                              const float acc[2][4][4],
                                              const float2* bias2, float* ob)
{
    const int r0 = wm * 32 + (lane >> 2);
    const int cb = wn * 32 + (lane & 3) * 2;
    #pragma unroll
    for (int j = 0; j < 4; j++) {
        const int col = cb + j * 8;
        #pragma unroll
        for (int h = 0; h < 2; h++) {
            float* p0 = ob + (size_t)(r0 + h * 16) * C_ + col;
            float* p1 = ob + (size_t)(r0 + h * 16 + 8) * C_ + col;
            *(float2*)p0 = make_float2(acc[h][j][0] + bias2[j].x,
                                       acc[h][j][1] + bias2[j].y);
            *(float2*)p1 = make_float2(acc[h][j][2] + bias2[j].x,
                                       acc[h][j][3] + bias2[j].y);
        }
    }
}

// ---------------------------------------------------------------------------
// GEMM2: persistent, bf16 pre-split A, double-buffered.
// ---------------------------------------------------------------------------
__global__ void __launch_bounds__(256, 1)
tc_gemm_bf_p(const __nv_bfloat16* __restrict__ Ah,
             const __nv_bfloat16* __restrict__ Al,
             const __nv_bfloat16* __restrict__ Wh,
             const __nv_bfloat16* __restrict__ Wl,
             const float* __restrict__ bias,
             float* __restrict__ out)
{
    extern __shared__ char smem[];
    const uint32_t sb = smem_u32(smem);
    const int tid  = threadIdx.x;
    const int lane = tid & 31;
    const int wid  = tid >> 5;
    const int wm   = wid & 1;
    const int wn   = wid >> 1;

    const int cb = wn * 32 + (lane & 3) * 2;
    float2 bias2[4];
    #pragma unroll
    for (int j = 0; j < 4; j++) bias2[j] = *(const float2*)(bias + cb + j * 8);

    load_B_async(sb, tid, Wh, Wl);
    int t = blockIdx.x;
    load_A_async(sb + SM_A0, tid, t, Ah, Al);
    cp_commit(); cp_wait0();
    __syncthreads();

    uint32_t abase = sb + SM_A0;
    for (; t < NTILE; t += GRIDP) {
        const int tn = t + GRIDP;
        const uint32_t anext = sb + (abase == sb + SM_A0 ? SM_A1 : SM_A0);
        if (tn < NTILE) {                       // prefetch into other buffer
            load_A_async(anext, tid, tn, Ah, Al);
            cp_commit();
        }

        float acc[2][4][4];
        gemm_mainloop(abase, sb, lane, wm, wn, acc);
        gemm_epilogue(lane, wm, wn, acc, bias2,
                      out + (size_t)t * MTILE * C_);

        cp_wait0();
        __syncthreads();
        abase = anext;
    }
}

// ---------------------------------------------------------------------------
// GEMM1: persistent, fp32 A, register-staged LDG + convert, double-buffered.
// ---------------------------------------------------------------------------
__device__ __forceinline__ void convert_store_A(uint32_t abase, const float4* ra,
                                                int tid) {
    #pragma unroll
    for (int it = 0; it < 8; it++) {
        const int i = tid + it * 256;       // 0..2047
        const int row = i >> 5, c4 = i & 31;
        const float4 a = ra[it];
        __nv_bfloat16 h0 = __float2bfloat16_rn(a.x);
        __nv_bfloat16 h1 = __float2bfloat16_rn(a.y);
        __nv_bfloat16 h2 = __float2bfloat16_rn(a.z);
        __nv_bfloat16 h3 = __float2bfloat16_rn(a.w);
        __nv_bfloat16 l0 = __float2bfloat16_rn(a.x - __bfloat162float(h0));
        __nv_bfloat16 l1 = __float2bfloat16_rn(a.y - __bfloat162float(h1));
        __nv_bfloat16 l2 = __float2bfloat16_rn(a.z - __bfloat162float(h2));
        __nv_bfloat16 l3 = __float2bfloat16_rn(a.w - __bfloat162float(h3));
        uint64_t hv = (uint64_t)__bfloat16_as_ushort(h0)
                    | ((uint64_t)__bfloat16_as_ushort(h1) << 16)
                    | ((uint64_t)__bfloat16_as_ushort(h2) << 32)
                    | ((uint64_t)__bfloat16_as_ushort(h3) << 48);
        uint64_t lv = (uint64_t)__bfloat16_as_ushort(l0)
                    | ((uint64_t)__bfloat16_as_ushort(l1) << 16)
                    | ((uint64_t)__bfloat16_as_ushort(l2) << 32)
                    | ((uint64_t)__bfloat16_as_ushort(l3) << 48);
        const uint32_t off = row * (STRIDE * 2) + c4 * 8;
        asm volatile("st.shared.b64 [%0], %1;" :: "r"(abase + off), "l"(hv) : "memory");
        asm volatile("st.shared.b64 [%0], %1;" :: "r"(abase + ABUF + off), "l"(lv) : "memory");
    }
}

__global__ void __launch_bounds__(256, 1)
tc_gemm_f32_p(const float* __restrict__ A,
              const __nv_bfloat16* __restrict__ Wh,
              const __nv_bfloat16* __restrict__ Wl,
              const float* __restrict__ bias,
              float* __restrict__ out)
{
    extern __shared__ char smem[];
    const uint32_t sb = smem_u32(smem);
    const int tid  = threadIdx.x;
    const int lane = tid & 31;
    const int wid  = tid >> 5;
    const int wm   = wid & 1;
    const int wn   = wid >> 1;

    const int cb = wn * 32 + (lane & 3) * 2;
    float2 bias2[4];
    #pragma unroll
    for (int j = 0; j < 4; j++) bias2[j] = *(const float2*)(bias + cb + j * 8);

    load_B_async(sb, tid, Wh, Wl);
    cp_commit();

    int t = blockIdx.x;
    float4 ra[8];
    {
        const float4* Ab = (const float4*)(A + (size_t)t * MTILE * C_);
        #pragma unroll
        for (int it = 0; it < 8; it++) ra[it] = Ab[tid + it * 256];
    }
    convert_store_A(sb + SM_A0, ra, tid);
    cp_wait0();
    __syncthreads();

    uint32_t abase = sb + SM_A0;
    for (; t < NTILE; t += GRIDP) {
        const int tn = t + GRIDP;
        const uint32_t anext = sb + (abase == sb + SM_A0 ? SM_A1 : SM_A0);
        if (tn < NTILE) {                       // LDGs hidden behind mainloop
            const float4* Ab = (const float4*)(A + (size_t)tn * MTILE * C_);
            #pragma unroll
            for (int it = 0; it < 8; it++) ra[it] = Ab[tid + it * 256];
        }

        float acc[2][4][4];
        gemm_mainloop(abase, sb, lane, wm, wn, acc);
        gemm_epilogue(lane, wm, wn, acc, bias2,
                      out + (size_t)t * MTILE * C_);

        if (tn < NTILE) convert_store_A(anext, ra, tid);
        __syncthreads();
        abase = anext;
    }
}

// ---------------------------------------------------------------------------
// Superpixel-gated 7x7 neighborhood aggregation. Warp per pixel.
// Output written as bf16 hi/lo split (feeds gemm2 directly).
// ---------------------------------------------------------------------------
__global__ void __launch_bounds__(256) agg_kernel(const float* __restrict__ v,
                                                  const float* __restrict__ attn,
                                                  const int*   __restrict__ sp,
                                                  __nv_bfloat16* __restrict__ outh,
                                                  __nv_bfloat16* __restrict__ outl)
{
    const int lane = threadIdx.x & 31;
    const int wid  = threadIdx.x >> 5;
    const int pix  = blockIdx.x * 8 + wid;
    const int x = pix & 127;
    const int y = (pix >> 7) & 127;
    const int b = pix >> 14;

    const int*   spb = sp + (b << 14);
    const float* vb  = v + (((size_t)b << 14) * C_);
    const int spc = spb[(y << 7) | x];

    int si = y - 3; si = si < 0 ? 0 : (si > HW_ - 7 ? HW_ - 7 : si);
    int sj = x - 3; sj = sj < 0 ? 0 : (sj > HW_ - 7 ? HW_ - 7 : sj);
    const int base_np = si * HW_ + sj;

    int k1 = lane;
    int ki1 = (k1 * 37) >> 8;
    unsigned m0 = __ballot_sync(0xffffffffu,
                                spb[base_np + ki1 * HW_ + (k1 - ki1 * 7)] == spc);
    int k2 = lane + 32; int k2c = k2 > 48 ? 48 : k2;
    int ki2 = (k2c * 37) >> 8;
    unsigned m1 = __ballot_sync(0xffffffffu,
        (k2 < 49) && (spb[base_np + ki2 * HW_ + (k2c - ki2 * 7)] == spc));

    const float* ab = attn +
        ((((size_t)(b * 4 + (lane >> 3)) * HW_ + y) * HW_ + x)) * 49;

    float4 acc = make_float4(0.f, 0.f, 0.f, 0.f);
    while (m0) {
        int k = __ffs(m0) - 1; m0 &= m0 - 1;
        int ki = (k * 37) >> 8;
        int np = base_np + ki * HW_ + (k - ki * 7);
        float a = __ldg(ab + k);
        float4 vv = *(const float4*)(vb + (size_t)np * C_ + lane * 4);
        acc.x += a * vv.x; acc.y += a * vv.y;
        acc.z += a * vv.z; acc.w += a * vv.w;
    }
    while (m1) {
        int k = (__ffs(m1) - 1) + 32; m1 &= m1 - 1;
        int ki = (k * 37) >> 8;
        int np = base_np + ki * HW_ + (k - ki * 7);
        float a = __ldg(ab + k);
        float4 vv = *(const float4*)(vb + (size_t)np * C_ + lane * 4);
        acc.x += a * vv.x; acc.y += a * vv.y;
        acc.z += a * vv.z; acc.w += a * vv.w;
    }

    __nv_bfloat16 h0 = __float2bfloat16_rn(acc.x);
    __nv_bfloat16 h1 = __float2bfloat16_rn(acc.y);
    __nv_bfloat16 h2 = __float2bfloat16_rn(acc.z);
    __nv_bfloat16 h3 = __float2bfloat16_rn(acc.w);
    __nv_bfloat16 l0 = __float2bfloat16_rn(acc.x - __bfloat162float(h0));
    __nv_bfloat16 l1 = __float2bfloat16_rn(acc.y - __bfloat162float(h1));
    __nv_bfloat16 l2 = __float2bfloat16_rn(acc.z - __bfloat162float(h2));
    __nv_bfloat16 l3 = __float2bfloat16_rn(acc.w - __bfloat162float(h3));
    uint2 hv, lv;
    hv.x = (uint32_t)__bfloat16_as_ushort(h0) | ((uint32_t)__bfloat16_as_ushort(h1) << 16);
    hv.y = (uint32_t)__bfloat16_as_ushort(h2) | ((uint32_t)__bfloat16_as_ushort(h3) << 16);
    lv.x = (uint32_t)__bfloat16_as_ushort(l0) | ((uint32_t)__bfloat16_as_ushort(l1) << 16);
    lv.y = (uint32_t)__bfloat16_as_ushort(l2) | ((uint32_t)__bfloat16_as_ushort(l3) << 16);
    *(uint2*)(outh + (size_t)pix * C_ + lane * 4) = hv;
    *(uint2*)(outl + (size_t)pix * C_ + lane * 4) = lv;
}

// ---------------------------------------------------------------------------
// Launch
// ---------------------------------------------------------------------------
extern "C" void kernel_launch(void* const* d_in, const int* in_sizes, int n_in,
                              void* d_out, int out_size)
{
    const float* x    = (const float*)d_in[0];
    const float* attn = (const float*)d_in[1];
    const int*   sp   = (const int*)  d_in[2];
    const float* Wv   = (const float*)d_in[3];
    const float* bv   = (const float*)d_in[4];
    const float* Wp   = (const float*)d_in[5];
    const float* bp   = (const float*)d_in[6];
    float*       out  = (float*)d_out;

    float* vbuf = nullptr;
    __nv_bfloat16 *aggh = nullptr, *aggl = nullptr, *wh = nullptr, *wl = nullptr;
    cudaGetSymbolAddress((void**)&vbuf, g_v);
    cudaGetSymbolAddress((void**)&aggh, g_aggh);
    cudaGetSymbolAddress((void**)&aggl, g_aggl);
    cudaGetSymbolAddress((void**)&wh, g_wh);
    cudaGetSymbolAddress((void**)&wl, g_wl);

    cudaFuncSetAttribute(tc_gemm_f32_p, cudaFuncAttributeMaxDynamicSharedMemorySize, SM_TOTAL);
    cudaFuncSetAttribute(tc_gemm_bf_p, cudaFuncAttributeMaxDynamicSharedMemorySize, SM_TOTAL);

    prep_w<<<2, 256>>>(Wv, Wp);
    tc_gemm_f32_p<<<GRIDP, 256, SM_TOTAL>>>(x, wh, wl, bv, vbuf);
    agg_kernel<<<NPIX / 8, 256>>>(vbuf, attn, sp, aggh, aggl);
    tc_gemm_bf_p<<<GRIDP, 256, SM_TOTAL>>>(aggh, aggl, wh + C_ * C_,
                                           wl + C_ * C_, bp, out);
}